// round 1
// baseline (speedup 1.0000x reference)
#include <cuda_runtime.h>
#include <math.h>
#include <stdint.h>

// RoPE: X (L=2048, D=4096, N=4) fp32, row-major.
// out[:, :half]  = cos*x1 - sin*x2
// out[:, half:]  = sin*x1 + cos*x2
// theta_i = 10000^(i/2048), ang = (l+1)*theta_i  (all fp32 in the reference)

#define L_DIM    2048
#define D_DIM    4096
#define HALF_DIM 2048   // D/2
#define N_DIM    4

__device__ float g_theta[HALF_DIM];

// Compute theta in double, round once to fp32 (correctly-rounded fp32 theta,
// matching jnp.power(10000, i/2048) computed in float32 up to its own rounding).
__global__ void theta_init_kernel() {
    int i = blockIdx.x * blockDim.x + threadIdx.x;
    if (i < HALF_DIM) {
        double e = (double)i * (1.0 / 2048.0);   // exact (i/2^11)
        g_theta[i] = (float)pow(10000.0, e);
    }
}

__global__ __launch_bounds__(256)
void rope_kernel(const float4* __restrict__ X, float4* __restrict__ out) {
    int idx = blockIdx.x * blockDim.x + threadIdx.x;   // 0 .. L*HALF-1
    int l = idx >> 11;          // / 2048
    int i = idx & (HALF_DIM - 1);

    // float4 index of (l, d=i, n=0..3)
    int base = l * D_DIM + i;           // in float4 units (N=4 floats per float4)
    float4 x1 = X[base];
    float4 x2 = X[base + HALF_DIM];

    // ang exactly as the reference: fp32 pos * fp32 theta, one IEEE fp32 multiply
    float theta = g_theta[i];
    float ang = (float)(l + 1) * theta;

    // Accurate range reduction of the *exact* value of the fp32 angle, in double.
    // |ang| < 2.1e7 < 2^53, so this is exact to ~2e-9 rad.
    double ad = (double)ang;
    double q  = rint(ad * 0.15915494309189535);      // 1/(2*pi)
    float  r  = (float)(fma(q, -6.283185307179586, ad));

    float s, c;
    sincosf(r, &s, &c);   // |r| <= pi: fast polynomial path, ~1 ulp

    float4 o1, o2;
    o1.x = c * x1.x - s * x2.x;
    o1.y = c * x1.y - s * x2.y;
    o1.z = c * x1.z - s * x2.z;
    o1.w = c * x1.w - s * x2.w;

    o2.x = s * x1.x + c * x2.x;
    o2.y = s * x1.y + c * x2.y;
    o2.z = s * x1.z + c * x2.z;
    o2.w = s * x1.w + c * x2.w;

    out[base]            = o1;
    out[base + HALF_DIM] = o2;
}

extern "C" void kernel_launch(void* const* d_in, const int* in_sizes, int n_in,
                              void* d_out, int out_size) {
    const float4* X   = (const float4*)d_in[0];
    float4*       out = (float4*)d_out;

    theta_init_kernel<<<(HALF_DIM + 255) / 256, 256>>>();

    int total = L_DIM * HALF_DIM;            // 4,194,304 threads
    rope_kernel<<<total / 256, 256>>>(X, out);
}

// round 2
// speedup vs baseline: 1.1474x; 1.1474x over previous
#include <cuda_runtime.h>
#include <math.h>
#include <stdint.h>

// RoPE: X (L=2048, D=4096, N=4) fp32, row-major.
// out[:, :half]  = cos*x1 - sin*x2 ; out[:, half:] = sin*x1 + cos*x2
// theta_i = 10000^(i/2048), ang = (l+1)*theta_i  (fp32 in the reference)
//
// Single kernel. theta rebuilt per-thread as a double-float product of
// host-computed constants c_k = 10000^(2^k/2048) over the bits of i
// (~2^-43 relative error -> rounds to the same fp32 as double pow).

#define L_DIM 2048
#define D4    4096      // float4s per (l) row (D floats, N=4 floats per float4)
#define HALF  2048
#define G     4         // l-values per thread

struct ThetaC { float hi[11]; float lo[11]; };

__global__ __launch_bounds__(256)
void rope_kernel(const float4* __restrict__ X, float4* __restrict__ out, ThetaC tc) {
    int t  = blockIdx.x * blockDim.x + threadIdx.x;   // 0 .. (L/G)*HALF - 1
    int i  = t & (HALF - 1);                          // rotary index
    int l0 = (t >> 11) * G;                           // first l for this thread

    // ---- double-float theta = prod_{bit k of i} c_k -------------------
    float th = 1.0f, tl = 0.0f;
    #pragma unroll
    for (int k = 0; k < 11; k++) {
        if (i & (1 << k)) {
            float bh = tc.hi[k], bl = tc.lo[k];
            float p  = th * bh;
            float e  = fmaf(th, bh, -p);
            e        = fmaf(th, bl, e);
            e        = fmaf(tl, bh, e);
            float s  = p + e;
            tl       = (p - s) + e;
            th       = s;
        }
    }
    float theta = th + tl;   // correctly-rounded fp32 theta

    // ---- front-batched loads (MLP) ------------------------------------
    int base = l0 * D4 + i;
    float4 x1[G], x2[G];
    #pragma unroll
    for (int k = 0; k < G; k++) {
        x1[k] = X[base + k * D4];
        x2[k] = X[base + k * D4 + HALF];
    }

    // ---- rotate --------------------------------------------------------
    #pragma unroll
    for (int k = 0; k < G; k++) {
        // exactly one fp32 multiply, as in the reference
        float ang = (float)(l0 + k + 1) * theta;

        // exact-angle range reduction in double (|ang| < 2.1e7 << 2^53)
        double ad = (double)ang;
        double q  = rint(ad * 0.15915494309189535);          // 1/(2*pi)
        float  r  = (float)fma(q, -6.283185307179586, ad);

        float s, c;
        sincosf(r, &s, &c);   // |r| <= pi: fast polynomial path

        float4 a = x1[k], b = x2[k], o1, o2;
        o1.x = c * a.x - s * b.x;  o1.y = c * a.y - s * b.y;
        o1.z = c * a.z - s * b.z;  o1.w = c * a.w - s * b.w;
        o2.x = s * a.x + c * b.x;  o2.y = s * a.y + c * b.y;
        o2.z = s * a.z + c * b.z;  o2.w = s * a.w + c * b.w;

        out[base + k * D4]        = o1;
        out[base + k * D4 + HALF] = o2;
    }
}

extern "C" void kernel_launch(void* const* d_in, const int* in_sizes, int n_in,
                              void* d_out, int out_size) {
    const float4* X   = (const float4*)d_in[0];
    float4*       out = (float4*)d_out;

    ThetaC tc;
    for (int k = 0; k < 11; k++) {
        double c = pow(10000.0, (double)(1 << k) / 2048.0);
        tc.hi[k] = (float)c;
        tc.lo[k] = (float)(c - (double)tc.hi[k]);
    }

    int total = (L_DIM / G) * HALF;           // 1,048,576 threads
    rope_kernel<<<total / 256, 256>>>(X, out, tc);
}